// round 6
// baseline (speedup 1.0000x reference)
#include <cuda_runtime.h>
#include <math.h>

#define NN 100000
#define NE 3200000
#define DF 128
#define HID 16
#define NC 2
#define GN 64               // nodes per gemm1 block

// ---------------- scratch (no allocations allowed) ----------------
__device__ float  g_deg[NN];
__device__ float  g_dinv[NN];
__device__ float4 g_h1s[NN * 4];   // (x@W1) * dinv
__device__ float4 g_acc1[NN * 4];  // layer-1 aggregate (init = self-loop term)
__device__ float2 g_h2s[NN];       // (relu@W2) * dinv
__device__ float2 g_acc2[NN];      // layer-2 aggregate

// ---------------- kernels ----------------

__global__ void k_init_deg() {
    int i = blockIdx.x * blockDim.x + threadIdx.x;
    if (i < NN) g_deg[i] = 1.0f;  // self-loop
}

__global__ void k_deg(const int* __restrict__ dst) {
    int e = blockIdx.x * blockDim.x + threadIdx.x;
    if (e < NE) atomicAdd(&g_deg[dst[e]], 1.0f);  // RED, no return
}

__global__ void k_dinv() {
    int i = blockIdx.x * blockDim.x + threadIdx.x;
    if (i < NN) g_dinv[i] = rsqrtf(g_deg[i]);  // deg >= 1 always
}

// ---------------- GEMM1 (smem-staged, coalesced) ----------------
// h1s[i] = acc1[i] = (x[i] @ W1) * dinv[i]
__global__ void k_gemm1(const float* __restrict__ x, const float* __restrict__ W1) {
    __shared__ __align__(16) float W1s[DF * HID];   // 8 KB
    __shared__ __align__(16) float XS[GN * 132];    // padded rows: conflict-free
    int tid = threadIdx.x;
    int base = blockIdx.x * GN;
    int nb = NN - base; if (nb > GN) nb = GN;

    for (int i = tid; i < DF * HID; i += 256) W1s[i] = W1[i];
    const float4* xg = (const float4*)(x + (size_t)base * DF);
    for (int f = tid; f < nb * 32; f += 256) {     // fully coalesced LDG.128
        int r = f >> 5, k = f & 31;
        *(float4*)&XS[r * 132 + k * 4] = xg[f];
    }
    __syncthreads();

    int n = tid >> 2, c = tid & 3;
    if (n >= nb) return;
    int node = base + n;
    float4 acc = make_float4(0.f, 0.f, 0.f, 0.f);
    const float* xr = &XS[n * 132];
#pragma unroll 4
    for (int k4 = 0; k4 < 32; k4++) {
        float4 xv = *(const float4*)&xr[k4 * 4];
#pragma unroll
        for (int j = 0; j < 4; j++) {
            float xs = (j == 0) ? xv.x : (j == 1) ? xv.y : (j == 2) ? xv.z : xv.w;
            float4 wq = *(const float4*)&W1s[(k4 * 4 + j) * HID + c * 4];
            acc.x = fmaf(xs, wq.x, acc.x);
            acc.y = fmaf(xs, wq.y, acc.y);
            acc.z = fmaf(xs, wq.z, acc.z);
            acc.w = fmaf(xs, wq.w, acc.w);
        }
    }
    float di = g_dinv[node];
    acc.x *= di; acc.y *= di; acc.z *= di; acc.w *= di;
    g_h1s[node * 4 + c] = acc;
    g_acc1[node * 4 + c] = acc;   // self-loop init
}

// ---------------- layer-1 scatter: 1 thread per edge, 4 v4 REDs ----------------
__global__ void k_scatter1(const int* __restrict__ src, const int* __restrict__ dst) {
    int e = blockIdx.x * blockDim.x + threadIdx.x;
    if (e >= NE) return;
    int s = src[e];
    int d = dst[e];
    const float4* vp = &g_h1s[s * 4];
    float4* p = &g_acc1[d * 4];
    float4 v0 = vp[0], v1 = vp[1], v2 = vp[2], v3 = vp[3];
    asm volatile("red.global.add.v4.f32 [%0], {%1, %2, %3, %4};"
                 :: "l"(p + 0), "f"(v0.x), "f"(v0.y), "f"(v0.z), "f"(v0.w) : "memory");
    asm volatile("red.global.add.v4.f32 [%0], {%1, %2, %3, %4};"
                 :: "l"(p + 1), "f"(v1.x), "f"(v1.y), "f"(v1.z), "f"(v1.w) : "memory");
    asm volatile("red.global.add.v4.f32 [%0], {%1, %2, %3, %4};"
                 :: "l"(p + 2), "f"(v2.x), "f"(v2.y), "f"(v2.z), "f"(v2.w) : "memory");
    asm volatile("red.global.add.v4.f32 [%0], {%1, %2, %3, %4};"
                 :: "l"(p + 3), "f"(v3.x), "f"(v3.y), "f"(v3.z), "f"(v3.w) : "memory");
}

// Per node: finish layer1 (scale + bias + relu), apply W2, pre-scale for layer2.
__global__ void k_finish1(const float* __restrict__ b1, const float* __restrict__ W2) {
    int i = blockIdx.x * blockDim.x + threadIdx.x;
    if (i >= NN) return;
    float di = g_dinv[i];
    float z0 = 0.0f, z1 = 0.0f;
#pragma unroll
    for (int q = 0; q < 4; q++) {
        float4 a = g_acc1[i * 4 + q];
        float av[4] = {a.x, a.y, a.z, a.w};
#pragma unroll
        for (int j = 0; j < 4; j++) {
            int f = q * 4 + j;
            float v = fmaxf(fmaf(di, av[j], __ldg(&b1[f])), 0.0f);
            z0 = fmaf(v, __ldg(&W2[f * NC + 0]), z0);
            z1 = fmaf(v, __ldg(&W2[f * NC + 1]), z1);
        }
    }
    float2 h;
    h.x = z0 * di;
    h.y = z1 * di;
    g_h2s[i] = h;
    g_acc2[i] = h;  // self-loop init
}

// ---------------- layer-2 scatter: 1 thread per edge, 1 v2 RED ----------------
__global__ void k_scatter2(const int* __restrict__ src, const int* __restrict__ dst) {
    int e = blockIdx.x * blockDim.x + threadIdx.x;
    if (e >= NE) return;
    int s = src[e];
    int d = dst[e];
    float2 v = g_h2s[s];
    float2* p = &g_acc2[d];
    asm volatile("red.global.add.v2.f32 [%0], {%1, %2};"
                 :: "l"(p), "f"(v.x), "f"(v.y) : "memory");
}

// Finish layer 2 + log_softmax (2 classes).
__global__ void k_final(const float* __restrict__ b2, float* __restrict__ out) {
    int i = blockIdx.x * blockDim.x + threadIdx.x;
    if (i >= NN) return;
    float di = g_dinv[i];
    float2 a = g_acc2[i];
    float z0 = fmaf(di, a.x, __ldg(&b2[0]));
    float z1 = fmaf(di, a.y, __ldg(&b2[1]));
    float m = fmaxf(z0, z1);
    float lse = m + logf(expf(z0 - m) + expf(z1 - m));
    float2 o;
    o.x = z0 - lse;
    o.y = z1 - lse;
    ((float2*)out)[i] = o;
}

// ---------------- launch ----------------

extern "C" void kernel_launch(void* const* d_in, const int* in_sizes, int n_in,
                              void* d_out, int out_size) {
    const float* x = 0; const float* W1 = 0; const float* b1 = 0;
    const float* W2 = 0; const float* b2 = 0; const int* ei = 0;
    for (int i = 0; i < n_in; i++) {
        long long s = in_sizes[i];
        if (s == (long long)NN * DF)      x  = (const float*)d_in[i];
        else if (s == DF * HID)           W1 = (const float*)d_in[i];
        else if (s == HID)                b1 = (const float*)d_in[i];
        else if (s == HID * NC)           W2 = (const float*)d_in[i];
        else if (s == NC)                 b2 = (const float*)d_in[i];
        else if (s == 2LL * NE)           ei = (const int*)d_in[i];
    }
    const int* src = ei;        // row 0
    const int* dst = ei + NE;   // row 1

    const int T = 256;
    const int NBn = (NN + T - 1) / T;
    const int NBe = (NE + T - 1) / T;

    k_init_deg<<<NBn, T>>>();
    k_deg<<<NBe, T>>>(dst);
    k_dinv<<<NBn, T>>>();
    k_gemm1<<<(NN + GN - 1) / GN, 256>>>(x, W1);
    k_scatter1<<<NBe, T>>>(src, dst);
    k_finish1<<<NBn, T>>>(b1, W2);
    k_scatter2<<<NBe, T>>>(src, dst);
    k_final<<<NBn, T>>>(b2, (float*)d_out);
}